// round 8
// baseline (speedup 1.0000x reference)
#include <cuda_runtime.h>
#include <cuda_fp16.h>
#include <cstdint>

// ============================================================================
// ScaledDotProductAttention  B=4 H=16 S=2048 D=128, causal, fp32 in/out
// FlashAttention-2, mma.sync.m16n8k16 HMMA.
// R8 = R7 (Q single fp16, single-pass QK/PV, exp2 softmax, thread-partial l,
//      double-buffered 64-key tiles) with two latency levers:
//   * grid transposed to (q-tile, bh): one wave covers ~9 heads' full q-tile
//     sets -> K/V stays L2-resident (R7 showed zero cross-q-tile L2 reuse,
//     577MB DRAM = full logical volume).
//   * Q fragments loaded once into registers (ldmatrix in prologue); Q SMEM
//     overlays the K stage buffers -> smem 104 -> 70 KB, 8 fewer ldmatrix
//     per iteration on the QK critical path.
// Same arithmetic as R7 -> rel_err expected unchanged (3.7e-4).
// ============================================================================

static constexpr int SEQ = 2048;
static constexpr int DH  = 128;
static constexpr float SCALE_LOG2E = 0.08838834764831845f * 1.4426950408889634f;

static constexpr int LDH = 136;   // padded SMEM stride in halfs

// SMEM layout (half units): K 2-stage + V 2-stage; Q staged over K region.
enum : uint32_t {
    KHI_OFF = 0,                       // 2 stages x 64 rows (Q prologue overlay)
    VHI_OFF = KHI_OFF + 2 * 64 * LDH,  // 2 stages x 64 rows
    SMEM_HALVES = VHI_OFF + 2 * 64 * LDH
};
static constexpr uint32_t SMEM_BYTES = SMEM_HALVES * 2;   // 69632

// ---------------------------------------------------------------------------
__device__ __forceinline__ uint32_t cvta_s(const void* p) {
    uint32_t a;
    asm("{ .reg .u64 t; cvta.to.shared.u64 t, %1; cvt.u32.u64 %0, t; }"
        : "=r"(a) : "l"(p));
    return a;
}

__device__ __forceinline__ float ex2f(float x) {
    float r;
    asm("ex2.approx.f32 %0, %1;" : "=f"(r) : "f"(x));
    return r;
}

__device__ __forceinline__ void ldsm4(uint32_t r[4], uint32_t addr) {
    asm volatile("ldmatrix.sync.aligned.m8n8.x4.shared.b16 {%0,%1,%2,%3}, [%4];"
                 : "=r"(r[0]), "=r"(r[1]), "=r"(r[2]), "=r"(r[3]) : "r"(addr));
}

__device__ __forceinline__ void ldsm4t(uint32_t r[4], uint32_t addr) {
    asm volatile("ldmatrix.sync.aligned.m8n8.x4.trans.shared.b16 {%0,%1,%2,%3}, [%4];"
                 : "=r"(r[0]), "=r"(r[1]), "=r"(r[2]), "=r"(r[3]) : "r"(addr));
}

__device__ __forceinline__ void mma16816(float d[4], const uint32_t a[4],
                                         const uint32_t b[2]) {
    asm volatile(
        "mma.sync.aligned.m16n8k16.row.col.f32.f16.f16.f32 "
        "{%0,%1,%2,%3}, {%4,%5,%6,%7}, {%8,%9}, {%0,%1,%2,%3};"
        : "+f"(d[0]), "+f"(d[1]), "+f"(d[2]), "+f"(d[3])
        : "r"(a[0]), "r"(a[1]), "r"(a[2]), "r"(a[3]), "r"(b[0]), "r"(b[1]));
}

__device__ __forceinline__ uint32_t packh2(__half a, __half b) {
    return (uint32_t)__half_as_ushort(a) | ((uint32_t)__half_as_ushort(b) << 16);
}

// ---------------------------------------------------------------------------
__global__ void __launch_bounds__(256, 1)
fa2_hmma_kernel(const float* __restrict__ Qg, const float* __restrict__ Kg,
                const float* __restrict__ Vg, float* __restrict__ Og)
{
    extern __shared__ __half sm[];
    const uint32_t sb = cvta_s(sm);
    const int tid  = threadIdx.x;
    const int w    = tid >> 5;
    const int lane = tid & 31;
    const int g    = lane >> 2;    // row group 0..7
    const int c    = lane & 3;     // col pair 0..3
    const int qt   = 15 - (int)blockIdx.x;        // heavy q-tiles first
    const int bh   = blockIdx.y;
    const size_t base = (size_t)bh * SEQ * DH;
    const int qr0  = qt * 128;

    // ldmatrix per-lane address components
    const int a_row  = 16 * w + (lane & 7) + ((lane >> 3) & 1) * 8;
    const int a_col8 = (lane >> 4) * 8;
    const int bk_rowi = (lane & 7) + (lane >> 4) * 8;
    const int bk_col8 = ((lane >> 3) & 1) * 8;
    const int bv_rowi = (lane & 7) + ((lane >> 3) & 1) * 8;
    const int bv_col8 = (lane >> 4) * 8;

    // per-thread K/V load coordinates
    const int ld_row = tid >> 5;          // 0..7 base row, step 8
    const int ld_c4  = tid & 31;          // float4 index within 128-d row

    // ---- prologue: stage Q in (K-region) SMEM, then ldmatrix into regs -----
    #pragma unroll
    for (int i = 0; i < 16; i++) {
        int idx = tid + i * 256;
        int row = idx >> 5, c4 = idx & 31;
        float4 v = *(const float4*)(Qg + base + (size_t)(qr0 + row) * DH + 4 * c4);
        v.x *= SCALE_LOG2E; v.y *= SCALE_LOG2E;
        v.z *= SCALE_LOG2E; v.w *= SCALE_LOG2E;
        uint32_t p = row * LDH + 4 * c4;
        *(uint32_t*)&sm[KHI_OFF + p]     = packh2(__float2half_rn(v.x), __float2half_rn(v.y));
        *(uint32_t*)&sm[KHI_OFF + p + 2] = packh2(__float2half_rn(v.z), __float2half_rn(v.w));
    }
    __syncthreads();

    uint32_t qf[8][4];                    // persistent Q A-fragments
    #pragma unroll
    for (int s = 0; s < 8; s++) {
        uint32_t qa = sb + 2u * (uint32_t)(KHI_OFF + a_row * LDH + 16 * s + a_col8);
        ldsm4(qf[s], qa);
    }
    __syncthreads();                      // all warps done reading Q overlay

    const int nkt = 2 * (qt + 1);

    // ---- preload K/V tile 0 into stage 0 -----------------------------------
    #pragma unroll
    for (int i = 0; i < 8; i++) {
        int row = ld_row + 8 * i;
        size_t goff = base + (size_t)row * DH + 4 * ld_c4;
        float4 kv = *(const float4*)(Kg + goff);
        float4 vv = *(const float4*)(Vg + goff);
        uint32_t p = row * LDH + 4 * ld_c4;
        *(uint32_t*)&sm[KHI_OFF + p]     = packh2(__float2half_rn(kv.x), __float2half_rn(kv.y));
        *(uint32_t*)&sm[KHI_OFF + p + 2] = packh2(__float2half_rn(kv.z), __float2half_rn(kv.w));
        *(uint32_t*)&sm[VHI_OFF + p]     = packh2(__float2half_rn(vv.x), __float2half_rn(vv.y));
        *(uint32_t*)&sm[VHI_OFF + p + 2] = packh2(__float2half_rn(vv.z), __float2half_rn(vv.w));
    }

    float O_[16][4];
    #pragma unroll
    for (int n = 0; n < 16; n++)
        #pragma unroll
        for (int e = 0; e < 4; e++) O_[n][e] = 0.0f;
    float mA = -1e30f, mB = -1e30f, lA = 0.0f, lB = 0.0f;  // l thread-partial

    __syncthreads();

    for (int j = 0; j < nkt; j++) {
        const uint32_t kbuf = KHI_OFF + (uint32_t)(j & 1) * 64 * LDH;
        const uint32_t vbuf = VHI_OFF + (uint32_t)(j & 1) * 64 * LDH;

        // ---- prefetch tile j+1 into the other stage ------------------------
        if (j + 1 < nkt) {
            const uint32_t kn = KHI_OFF + (uint32_t)((j + 1) & 1) * 64 * LDH;
            const uint32_t vn = VHI_OFF + (uint32_t)((j + 1) & 1) * 64 * LDH;
            #pragma unroll
            for (int i = 0; i < 8; i++) {
                int row = ld_row + 8 * i;
                size_t goff = base + (size_t)(64 * (j + 1) + row) * DH + 4 * ld_c4;
                float4 kv = *(const float4*)(Kg + goff);
                float4 vv = *(const float4*)(Vg + goff);
                uint32_t p = row * LDH + 4 * ld_c4;
                *(uint32_t*)&sm[kn + p]     = packh2(__float2half_rn(kv.x), __float2half_rn(kv.y));
                *(uint32_t*)&sm[kn + p + 2] = packh2(__float2half_rn(kv.z), __float2half_rn(kv.w));
                *(uint32_t*)&sm[vn + p]     = packh2(__float2half_rn(vv.x), __float2half_rn(vv.y));
                *(uint32_t*)&sm[vn + p + 2] = packh2(__float2half_rn(vv.z), __float2half_rn(vv.w));
            }
        }

        // ---- S = Q K^T  (Q fragments resident in registers) ----------------
        float S_[8][4];
        #pragma unroll
        for (int n = 0; n < 8; n++)
            #pragma unroll
            for (int e = 0; e < 4; e++) S_[n][e] = 0.0f;

        #pragma unroll
        for (int s = 0; s < 8; s++) {
            #pragma unroll
            for (int t = 0; t < 4; t++) {
                uint32_t bhh[4];
                uint32_t ka = sb + 2u * (uint32_t)(kbuf + (16 * t + bk_rowi) * LDH
                                                   + 16 * s + bk_col8);
                ldsm4(bhh, ka);
                mma16816(S_[2 * t],     qf[s], bhh);
                mma16816(S_[2 * t + 1], qf[s], bhh + 2);
            }
        }

        // ---- causal mask (diagonal-overlap tiles only) ---------------------
        const int rowA = qr0 + 16 * w + g;
        const int rowB = rowA + 8;
        if (j >= 2 * qt) {
            int kb = 64 * j;
            #pragma unroll
            for (int n = 0; n < 8; n++) {
                #pragma unroll
                for (int e = 0; e < 2; e++) {
                    int key = kb + 8 * n + 2 * c + e;
                    if (key > rowA) S_[n][e]     = -1e30f;
                    if (key > rowB) S_[n][2 + e] = -1e30f;
                }
            }
        }

        // ---- online softmax (quad-local max; l thread-partial) -------------
        float mtA = -1e30f, mtB = -1e30f;
        #pragma unroll
        for (int n = 0; n < 8; n++) {
            mtA = fmaxf(mtA, fmaxf(S_[n][0], S_[n][1]));
            mtB = fmaxf(mtB, fmaxf(S_[n][2], S_[n][3]));
        }
        mtA = fmaxf(mtA, __shfl_xor_sync(0xffffffffu, mtA, 1));
        mtA = fmaxf(mtA, __shfl_xor_sync(0xffffffffu, mtA, 2));
        mtB = fmaxf(mtB, __shfl_xor_sync(0xffffffffu, mtB, 1));
        mtB = fmaxf(mtB, __shfl_xor_sync(0xffffffffu, mtB, 2));

        float mnA = fmaxf(mA, mtA), mnB = fmaxf(mB, mtB);
        float corrA = ex2f(mA - mnA), corrB = ex2f(mB - mnB);

        float sA = 0.0f, sB = 0.0f;
        #pragma unroll
        for (int n = 0; n < 8; n++) {
            S_[n][0] = ex2f(S_[n][0] - mnA);
            S_[n][1] = ex2f(S_[n][1] - mnA);
            S_[n][2] = ex2f(S_[n][2] - mnB);
            S_[n][3] = ex2f(S_[n][3] - mnB);
            sA += S_[n][0] + S_[n][1];
            sB += S_[n][2] + S_[n][3];
        }
        lA = lA * corrA + sA;  mA = mnA;
        lB = lB * corrB + sB;  mB = mnB;

        #pragma unroll
        for (int n = 0; n < 16; n++) {
            O_[n][0] *= corrA; O_[n][1] *= corrA;
            O_[n][2] *= corrB; O_[n][3] *= corrB;
        }

        // ---- P: C-layout -> fp16 A-fragments -------------------------------
        uint32_t ph[4][4];
        #pragma unroll
        for (int s = 0; s < 4; s++) {
            #pragma unroll
            for (int half_ : {0, 1}) {
                const float* src = S_[2 * s + half_];
                ph[s][2 * half_]     = packh2(__float2half_rn(src[0]),
                                              __float2half_rn(src[1]));
                ph[s][2 * half_ + 1] = packh2(__float2half_rn(src[2]),
                                              __float2half_rn(src[3]));
            }
        }

        // ---- O += P V  (single pass) ---------------------------------------
        #pragma unroll
        for (int s = 0; s < 4; s++) {
            #pragma unroll
            for (int t = 0; t < 8; t++) {
                uint32_t vh[4];
                uint32_t va = sb + 2u * (uint32_t)(vbuf + (16 * s + bv_rowi) * LDH
                                                   + 16 * t + bv_col8);
                ldsm4t(vh, va);
                mma16816(O_[2 * t],     ph[s], vh);
                mma16816(O_[2 * t + 1], ph[s], vh + 2);
            }
        }

        __syncthreads();   // publish prefetched tile j+1; free buffer j
    }

    // ---- epilogue: reduce l across quad, O /= l, store fp32 ----------------
    {
        lA += __shfl_xor_sync(0xffffffffu, lA, 1);
        lA += __shfl_xor_sync(0xffffffffu, lA, 2);
        lB += __shfl_xor_sync(0xffffffffu, lB, 1);
        lB += __shfl_xor_sync(0xffffffffu, lB, 2);
        float iA = 1.0f / lA, iB = 1.0f / lB;
        const int rowA = qr0 + 16 * w + g;
        float* oA = Og + base + (size_t)rowA * DH;
        float* oB = oA + 8 * DH;
        #pragma unroll
        for (int n = 0; n < 16; n++) {
            *(float2*)(oA + 8 * n + 2 * c) =
                make_float2(O_[n][0] * iA, O_[n][1] * iA);
            *(float2*)(oB + 8 * n + 2 * c) =
                make_float2(O_[n][2] * iB, O_[n][3] * iB);
        }
    }
}

// ---------------------------------------------------------------------------
extern "C" void kernel_launch(void* const* d_in, const int* in_sizes, int n_in,
                              void* d_out, int out_size) {
    const float* Q = (const float*)d_in[0];
    const float* K = (const float*)d_in[1];
    const float* V = (const float*)d_in[2];
    // d_in[3] = causal mask (known tril) — applied analytically in-kernel.
    float* O = (float*)d_out;

    cudaFuncSetAttribute(fa2_hmma_kernel,
                         cudaFuncAttributeMaxDynamicSharedMemorySize, SMEM_BYTES);

    // grid transposed: x = q-tile (16, heavy first), y = bh (64).
    // One wave (~148 CTAs) covers ~9 heads' full q-tile sets -> K/V L2-resident.
    dim3 grid(16, 64, 1);
    fa2_hmma_kernel<<<grid, 256, SMEM_BYTES>>>(Q, K, V, O);
}

// round 9
// speedup vs baseline: 1.3031x; 1.3031x over previous
#include <cuda_runtime.h>
#include <cuda_fp16.h>
#include <cstdint>

// ============================================================================
// ScaledDotProductAttention  B=4 H=16 S=2048 D=128, causal, fp32 in/out
// FlashAttention-2, mma.sync.m16n8k16 HMMA.
// R9 = exact R7 structure (grid (bh, qt) LPT order, Q fp16 in SMEM,
//      double-buffered 64-key tiles, single-pass QK/PV, exp2 softmax,
//      thread-partial l) + two exact-path cuts:
//   * warp-uniform skip of O-rescale/corr when no row saw a new max
//     (corr == 1 exactly; __any_sync keeps the branch warp-uniform);
//   * fused cvt.rn.f16x2.f32 convert+pack in P-pack / prefetch / Q prologue.
// R8 lesson: grid transpose broke LPT scheduling (+27% makespan); memory
// was never binding (double-buffer hides prefetch latency). Reverted.
// ============================================================================

static constexpr int SEQ = 2048;
static constexpr int DH  = 128;
static constexpr float SCALE_LOG2E = 0.08838834764831845f * 1.4426950408889634f;

static constexpr int LDH = 136;   // padded SMEM stride in halfs

// SMEM layout (half units)
enum : uint32_t {
    Q_OFF   = 0,
    KHI_OFF = Q_OFF + 128 * LDH,       // 2 stages x 64 rows
    VHI_OFF = KHI_OFF + 2 * 64 * LDH,  // 2 stages x 64 rows
    SMEM_HALVES = VHI_OFF + 2 * 64 * LDH
};
static constexpr uint32_t SMEM_BYTES = SMEM_HALVES * 2;   // 104448

// ---------------------------------------------------------------------------
__device__ __forceinline__ uint32_t cvta_s(const void* p) {
    uint32_t a;
    asm("{ .reg .u64 t; cvta.to.shared.u64 t, %1; cvt.u32.u64 %0, t; }"
        : "=r"(a) : "l"(p));
    return a;
}

__device__ __forceinline__ float ex2f(float x) {
    float r;
    asm("ex2.approx.f32 %0, %1;" : "=f"(r) : "f"(x));
    return r;
}

__device__ __forceinline__ void ldsm4(uint32_t r[4], uint32_t addr) {
    asm volatile("ldmatrix.sync.aligned.m8n8.x4.shared.b16 {%0,%1,%2,%3}, [%4];"
                 : "=r"(r[0]), "=r"(r[1]), "=r"(r[2]), "=r"(r[3]) : "r"(addr));
}

__device__ __forceinline__ void ldsm4t(uint32_t r[4], uint32_t addr) {
    asm volatile("ldmatrix.sync.aligned.m8n8.x4.trans.shared.b16 {%0,%1,%2,%3}, [%4];"
                 : "=r"(r[0]), "=r"(r[1]), "=r"(r[2]), "=r"(r[3]) : "r"(addr));
}

__device__ __forceinline__ void mma16816(float d[4], const uint32_t a[4],
                                         const uint32_t b[2]) {
    asm volatile(
        "mma.sync.aligned.m16n8k16.row.col.f32.f16.f16.f32 "
        "{%0,%1,%2,%3}, {%4,%5,%6,%7}, {%8,%9}, {%0,%1,%2,%3};"
        : "+f"(d[0]), "+f"(d[1]), "+f"(d[2]), "+f"(d[3])
        : "r"(a[0]), "r"(a[1]), "r"(a[2]), "r"(a[3]), "r"(b[0]), "r"(b[1]));
}

// fused f32x2 -> f16x2 convert+pack (single cvt.rn.f16x2.f32)
__device__ __forceinline__ uint32_t packf2(float a, float b) {
    __half2 h = __floats2half2_rn(a, b);
    return *reinterpret_cast<uint32_t*>(&h);
}

// ---------------------------------------------------------------------------
__global__ void __launch_bounds__(256, 1)
fa2_hmma_kernel(const float* __restrict__ Qg, const float* __restrict__ Kg,
                const float* __restrict__ Vg, float* __restrict__ Og)
{
    extern __shared__ __half sm[];
    const uint32_t sb = cvta_s(sm);
    const int tid  = threadIdx.x;
    const int w    = tid >> 5;
    const int lane = tid & 31;
    const int g    = lane >> 2;    // row group 0..7
    const int c    = lane & 3;     // col pair 0..3
    const int bh   = blockIdx.x;
    const int qt   = 15 - (int)blockIdx.y;        // heavy q-tiles first (LPT)
    const size_t base = (size_t)bh * SEQ * DH;
    const int qr0  = qt * 128;

    // ldmatrix per-lane address components
    const int a_row  = 16 * w + (lane & 7) + ((lane >> 3) & 1) * 8;
    const int a_col8 = (lane >> 4) * 8;
    const int bk_rowi = (lane & 7) + (lane >> 4) * 8;
    const int bk_col8 = ((lane >> 3) & 1) * 8;
    const int bv_rowi = (lane & 7) + ((lane >> 3) & 1) * 8;
    const int bv_col8 = (lane >> 4) * 8;

    // per-thread K/V load coordinates
    const int ld_row = tid >> 5;          // 0..7 base row, step 8
    const int ld_c4  = tid & 31;          // float4 index within 128-d row

    // ---- prologue: Q tile -> fp16 SMEM (pre-scaled by scale*log2e) ---------
    #pragma unroll
    for (int i = 0; i < 16; i++) {
        int idx = tid + i * 256;
        int row = idx >> 5, c4 = idx & 31;
        float4 v = *(const float4*)(Qg + base + (size_t)(qr0 + row) * DH + 4 * c4);
        uint32_t p = row * LDH + 4 * c4;
        *(uint32_t*)&sm[Q_OFF + p]     = packf2(v.x * SCALE_LOG2E, v.y * SCALE_LOG2E);
        *(uint32_t*)&sm[Q_OFF + p + 2] = packf2(v.z * SCALE_LOG2E, v.w * SCALE_LOG2E);
    }

    const int nkt = 2 * (qt + 1);

    // ---- preload K/V tile 0 into stage 0 -----------------------------------
    #pragma unroll
    for (int i = 0; i < 8; i++) {
        int row = ld_row + 8 * i;
        size_t goff = base + (size_t)row * DH + 4 * ld_c4;
        float4 kv = *(const float4*)(Kg + goff);
        float4 vv = *(const float4*)(Vg + goff);
        uint32_t p = row * LDH + 4 * ld_c4;
        *(uint32_t*)&sm[KHI_OFF + p]     = packf2(kv.x, kv.y);
        *(uint32_t*)&sm[KHI_OFF + p + 2] = packf2(kv.z, kv.w);
        *(uint32_t*)&sm[VHI_OFF + p]     = packf2(vv.x, vv.y);
        *(uint32_t*)&sm[VHI_OFF + p + 2] = packf2(vv.z, vv.w);
    }

    float O_[16][4];
    #pragma unroll
    for (int n = 0; n < 16; n++)
        #pragma unroll
        for (int e = 0; e < 4; e++) O_[n][e] = 0.0f;
    float mA = -1e30f, mB = -1e30f, lA = 0.0f, lB = 0.0f;  // l thread-partial

    __syncthreads();

    for (int j = 0; j < nkt; j++) {
        const uint32_t kbuf = KHI_OFF + (uint32_t)(j & 1) * 64 * LDH;
        const uint32_t vbuf = VHI_OFF + (uint32_t)(j & 1) * 64 * LDH;

        // ---- prefetch tile j+1 into the other stage ------------------------
        if (j + 1 < nkt) {
            const uint32_t kn = KHI_OFF + (uint32_t)((j + 1) & 1) * 64 * LDH;
            const uint32_t vn = VHI_OFF + (uint32_t)((j + 1) & 1) * 64 * LDH;
            #pragma unroll
            for (int i = 0; i < 8; i++) {
                int row = ld_row + 8 * i;
                size_t goff = base + (size_t)(64 * (j + 1) + row) * DH + 4 * ld_c4;
                float4 kv = *(const float4*)(Kg + goff);
                float4 vv = *(const float4*)(Vg + goff);
                uint32_t p = row * LDH + 4 * ld_c4;
                *(uint32_t*)&sm[kn + p]     = packf2(kv.x, kv.y);
                *(uint32_t*)&sm[kn + p + 2] = packf2(kv.z, kv.w);
                *(uint32_t*)&sm[vn + p]     = packf2(vv.x, vv.y);
                *(uint32_t*)&sm[vn + p + 2] = packf2(vv.z, vv.w);
            }
        }

        // ---- S = Q K^T  (single pass, log2-domain scores) ------------------
        float S_[8][4];
        #pragma unroll
        for (int n = 0; n < 8; n++)
            #pragma unroll
            for (int e = 0; e < 4; e++) S_[n][e] = 0.0f;

        #pragma unroll
        for (int s = 0; s < 8; s++) {
            uint32_t qh[4];
            uint32_t qa = sb + 2u * (uint32_t)(Q_OFF + a_row * LDH + 16 * s + a_col8);
            ldsm4(qh, qa);
            #pragma unroll
            for (int t = 0; t < 4; t++) {
                uint32_t bhh[4];
                uint32_t ka = sb + 2u * (uint32_t)(kbuf + (16 * t + bk_rowi) * LDH
                                                   + 16 * s + bk_col8);
                ldsm4(bhh, ka);
                mma16816(S_[2 * t],     qh, bhh);
                mma16816(S_[2 * t + 1], qh, bhh + 2);
            }
        }

        // ---- causal mask (diagonal-overlap tiles only) ---------------------
        const int rowA = qr0 + 16 * w + g;
        const int rowB = rowA + 8;
        if (j >= 2 * qt) {
            int kb = 64 * j;
            #pragma unroll
            for (int n = 0; n < 8; n++) {
                #pragma unroll
                for (int e = 0; e < 2; e++) {
                    int key = kb + 8 * n + 2 * c + e;
                    if (key > rowA) S_[n][e]     = -1e30f;
                    if (key > rowB) S_[n][2 + e] = -1e30f;
                }
            }
        }

        // ---- online softmax (quad-local max; warp-uniform rescale skip) ----
        float mtA = -1e30f, mtB = -1e30f;
        #pragma unroll
        for (int n = 0; n < 8; n++) {
            mtA = fmaxf(mtA, fmaxf(S_[n][0], S_[n][1]));
            mtB = fmaxf(mtB, fmaxf(S_[n][2], S_[n][3]));
        }
        mtA = fmaxf(mtA, __shfl_xor_sync(0xffffffffu, mtA, 1));
        mtA = fmaxf(mtA, __shfl_xor_sync(0xffffffffu, mtA, 2));
        mtB = fmaxf(mtB, __shfl_xor_sync(0xffffffffu, mtB, 1));
        mtB = fmaxf(mtB, __shfl_xor_sync(0xffffffffu, mtB, 2));

        float mnA = fmaxf(mA, mtA), mnB = fmaxf(mB, mtB);
        bool new_max = (mnA > mA) || (mnB > mB);

        if (__any_sync(0xffffffffu, new_max)) {
            float corrA = ex2f(mA - mnA), corrB = ex2f(mB - mnB);
            lA *= corrA;  lB *= corrB;
            #pragma unroll
            for (int n = 0; n < 16; n++) {
                O_[n][0] *= corrA; O_[n][1] *= corrA;
                O_[n][2] *= corrB; O_[n][3] *= corrB;
            }
            mA = mnA; mB = mnB;
        }
        // else: corr == 1 exactly; nothing to do.

        float sA = 0.0f, sB = 0.0f;
        #pragma unroll
        for (int n = 0; n < 8; n++) {
            S_[n][0] = ex2f(S_[n][0] - mA);
            S_[n][1] = ex2f(S_[n][1] - mA);
            S_[n][2] = ex2f(S_[n][2] - mB);
            S_[n][3] = ex2f(S_[n][3] - mB);
            sA += S_[n][0] + S_[n][1];
            sB += S_[n][2] + S_[n][3];
        }
        lA += sA;  lB += sB;               // thread-partial l

        // ---- P: C-layout -> fp16 A-fragments (fused f16x2 cvt) -------------
        uint32_t ph[4][4];
        #pragma unroll
        for (int s = 0; s < 4; s++) {
            #pragma unroll
            for (int half_ : {0, 1}) {
                const float* src = S_[2 * s + half_];
                ph[s][2 * half_]     = packf2(src[0], src[1]);
                ph[s][2 * half_ + 1] = packf2(src[2], src[3]);
            }
        }

        // ---- O += P V  (single pass) ---------------------------------------
        #pragma unroll
        for (int s = 0; s < 4; s++) {
            #pragma unroll
            for (int t = 0; t < 8; t++) {
                uint32_t vh[4];
                uint32_t va = sb + 2u * (uint32_t)(vbuf + (16 * s + bv_rowi) * LDH
                                                   + 16 * t + bv_col8);
                ldsm4t(vh, va);
                mma16816(O_[2 * t],     ph[s], vh);
                mma16816(O_[2 * t + 1], ph[s], vh + 2);
            }
        }

        __syncthreads();   // publish prefetched tile j+1; free buffer j
    }

    // ---- epilogue: reduce l across quad, O /= l, store fp32 ----------------
    {
        lA += __shfl_xor_sync(0xffffffffu, lA, 1);
        lA += __shfl_xor_sync(0xffffffffu, lA, 2);
        lB += __shfl_xor_sync(0xffffffffu, lB, 1);
        lB += __shfl_xor_sync(0xffffffffu, lB, 2);
        float iA = 1.0f / lA, iB = 1.0f / lB;
        const int rowA = qr0 + 16 * w + g;
        float* oA = Og + base + (size_t)rowA * DH;
        float* oB = oA + 8 * DH;
        #pragma unroll
        for (int n = 0; n < 16; n++) {
            *(float2*)(oA + 8 * n + 2 * c) =
                make_float2(O_[n][0] * iA, O_[n][1] * iA);
            *(float2*)(oB + 8 * n + 2 * c) =
                make_float2(O_[n][2] * iB, O_[n][3] * iB);
        }
    }
}

// ---------------------------------------------------------------------------
extern "C" void kernel_launch(void* const* d_in, const int* in_sizes, int n_in,
                              void* d_out, int out_size) {
    const float* Q = (const float*)d_in[0];
    const float* K = (const float*)d_in[1];
    const float* V = (const float*)d_in[2];
    // d_in[3] = causal mask (known tril) — applied analytically in-kernel.
    float* O = (float*)d_out;

    cudaFuncSetAttribute(fa2_hmma_kernel,
                         cudaFuncAttributeMaxDynamicSharedMemorySize, SMEM_BYTES);

    dim3 grid(64, 16, 1);   // LPT: heavy q-tiles first, bh fastest
    fa2_hmma_kernel<<<grid, 256, SMEM_BYTES>>>(Q, K, V, O);
}